// round 2
// baseline (speedup 1.0000x reference)
#include <cuda_runtime.h>
#include <cstdint>

// Problem constants
#define BB 2
#define TT 2048
#define CCH 1024
#define HH 16
#define DD 64
#define MROWS (BB * TT)       // 4096
#define NEG_BIG (-1e30f)

// Scratch (allocation-free: __device__ globals)
__device__ float g_qkv[(size_t)MROWS * 3 * CCH];  // [4096, 3072]
__device__ float g_att[(size_t)MROWS * CCH];      // [4096, 1024]

// ---------------------------------------------------------------------------
// SGEMM with fused bias: C[M,N] = A[M,K] @ B[K,N] + bias[N]
// BM=BN=128, BK=8, 256 threads, 8x8 per-thread microtile.
// Requires M%128==0, N%128==0, K%8==0 (true for all our shapes).
// ---------------------------------------------------------------------------
__global__ __launch_bounds__(256)
void sgemm_bias_kernel(const float* __restrict__ A, const float* __restrict__ B,
                       const float* __restrict__ bias, float* __restrict__ C,
                       int M, int N, int K) {
    constexpr int BM = 128, BN = 128, BK = 8, TM = 8, TN = 8;
    __shared__ float As[BK][BM];
    __shared__ float Bs[BK][BN];

    const int tid = threadIdx.x;
    const int tx = tid & 15;          // 0..15 (N direction)
    const int ty = tid >> 4;          // 0..15 (M direction)
    const int rowBase = blockIdx.y * BM;
    const int colBase = blockIdx.x * BN;

    // Load mapping
    const int aRow  = tid >> 1;        // 0..127
    const int aK4   = (tid & 1) * 4;   // 0 or 4
    const int bRow  = tid >> 5;        // 0..7
    const int bCol4 = (tid & 31) * 4;  // 0..124

    float acc[TM][TN];
#pragma unroll
    for (int i = 0; i < TM; i++)
#pragma unroll
        for (int j = 0; j < TN; j++) acc[i][j] = 0.f;

    for (int k0 = 0; k0 < K; k0 += BK) {
        float4 av = *reinterpret_cast<const float4*>(&A[(size_t)(rowBase + aRow) * K + k0 + aK4]);
        As[aK4 + 0][aRow] = av.x;
        As[aK4 + 1][aRow] = av.y;
        As[aK4 + 2][aRow] = av.z;
        As[aK4 + 3][aRow] = av.w;
        float4 bv = *reinterpret_cast<const float4*>(&B[(size_t)(k0 + bRow) * N + colBase + bCol4]);
        *reinterpret_cast<float4*>(&Bs[bRow][bCol4]) = bv;
        __syncthreads();

#pragma unroll
        for (int k = 0; k < BK; k++) {
            float ra[TM], rb[TN];
#pragma unroll
            for (int i = 0; i < TM; i++) ra[i] = As[k][ty * TM + i];
#pragma unroll
            for (int j = 0; j < TN; j++) rb[j] = Bs[k][tx * TN + j];
#pragma unroll
            for (int i = 0; i < TM; i++)
#pragma unroll
                for (int j = 0; j < TN; j++) acc[i][j] += ra[i] * rb[j];
        }
        __syncthreads();
    }

#pragma unroll
    for (int i = 0; i < TM; i++) {
        const int r = rowBase + ty * TM + i;
#pragma unroll
        for (int j = 0; j < TN; j += 4) {
            const int c = colBase + tx * TN + j;
            float4 o;
            o.x = acc[i][j + 0] + bias[c + 0];
            o.y = acc[i][j + 1] + bias[c + 1];
            o.z = acc[i][j + 2] + bias[c + 2];
            o.w = acc[i][j + 3] + bias[c + 3];
            *reinterpret_cast<float4*>(&C[(size_t)r * N + c]) = o;
        }
    }
}

// ---------------------------------------------------------------------------
// Causal flash attention: qkv [M, 3C] (q|k|v per head inside each third),
// out [M, C] in (b,t,h,d) layout (== transpose-back layout of reference).
// One thread per q row; BQ = BKV = 64; online softmax.
// ---------------------------------------------------------------------------
#define BQ 64
#define BKV 64
#define KSTR 68   // padded K/V row stride (floats) to break STS conflicts
#define SSTR 65   // padded score row stride

__global__ __launch_bounds__(BQ)
void attn_kernel(const float* __restrict__ qkv, float* __restrict__ out) {
    extern __shared__ float smem[];
    float* Ks = smem;                     // [BKV][KSTR]
    float* Vs = smem + BKV * KSTR;        // [BKV][KSTR]
    float* Ss = smem + 2 * BKV * KSTR;    // [BQ][SSTR]

    const int qb = blockIdx.x;   // q tile
    const int h  = blockIdx.y;
    const int b  = blockIdx.z;
    const int r  = threadIdx.x;  // q row within tile (0..63)
    const int qrow = qb * BQ + r;
    const size_t btq = (size_t)(b * TT + qrow);

    // Load this thread's q row into registers
    float q[DD];
    {
        const float* qp = &qkv[btq * (3 * CCH) + h * DD];
#pragma unroll
        for (int d = 0; d < DD; d += 4) {
            float4 v = *reinterpret_cast<const float4*>(&qp[d]);
            q[d] = v.x; q[d + 1] = v.y; q[d + 2] = v.z; q[d + 3] = v.w;
        }
    }

    float acc[DD];
#pragma unroll
    for (int d = 0; d < DD; d++) acc[d] = 0.f;
    float m = NEG_BIG, l = 0.f;
    const float scale = 0.125f;  // 1/sqrt(64)

    const int nkv = qb + 1;  // causal: only tiles <= diagonal
    for (int kt = 0; kt < nkv; kt++) {
        // Cooperative K/V tile load: 1024 float4s each, 16 iters x 64 threads
#pragma unroll
        for (int i = 0; i < 16; i++) {
            const int idx = i * 64 + r;       // 0..1023
            const int row = idx >> 4;         // 0..63
            const int c4  = (idx & 15) * 4;   // 0..60
            const size_t btk = (size_t)(b * TT + kt * BKV + row) * (3 * CCH) + h * DD + c4;
            *reinterpret_cast<float4*>(&Ks[row * KSTR + c4]) =
                *reinterpret_cast<const float4*>(&qkv[btk + CCH]);
            *reinterpret_cast<float4*>(&Vs[row * KSTR + c4]) =
                *reinterpret_cast<const float4*>(&qkv[btk + 2 * CCH]);
        }
        __syncthreads();

        // Scores for this thread's q row (broadcast smem reads)
        float mt = m;
        const bool diag = (kt == qb);
#pragma unroll 1
        for (int j = 0; j < BKV; j++) {
            const float* krow = &Ks[j * KSTR];
            float dot = 0.f;
#pragma unroll
            for (int d = 0; d < DD; d++) dot += q[d] * krow[d];
            float sv = dot * scale;
            if (diag && j > r) sv = NEG_BIG;
            Ss[r * SSTR + j] = sv;
            mt = fmaxf(mt, sv);
        }

        const float corr = __expf(m - mt);
        l *= corr;
#pragma unroll
        for (int d = 0; d < DD; d++) acc[d] *= corr;

#pragma unroll 1
        for (int j = 0; j < BKV; j++) {
            const float p = __expf(Ss[r * SSTR + j] - mt);
            l += p;
            const float* vrow = &Vs[j * KSTR];
#pragma unroll
            for (int d = 0; d < DD; d++) acc[d] += p * vrow[d];
        }
        m = mt;
        __syncthreads();
    }

    const float inv = 1.f / l;
    float* op = &out[btq * CCH + h * DD];
#pragma unroll
    for (int d = 0; d < DD; d += 4) {
        float4 o;
        o.x = acc[d] * inv; o.y = acc[d + 1] * inv;
        o.z = acc[d + 2] * inv; o.w = acc[d + 3] * inv;
        *reinterpret_cast<float4*>(&op[d]) = o;
    }
}

// ---------------------------------------------------------------------------
extern "C" void kernel_launch(void* const* d_in, const int* in_sizes, int n_in,
                              void* d_out, int out_size) {
    const float* x     = (const float*)d_in[0];
    const float* Wqkv  = (const float*)d_in[1];
    const float* bqkv  = (const float*)d_in[2];
    const float* Wproj = (const float*)d_in[3];
    const float* bproj = (const float*)d_in[4];
    float* out = (float*)d_out;

    float *qkv, *att;
    cudaGetSymbolAddress((void**)&qkv, g_qkv);
    cudaGetSymbolAddress((void**)&att, g_att);

    // 1) QKV projection: [4096,1024] @ [1024,3072] + bias
    {
        dim3 grid(3 * CCH / 128, MROWS / 128);
        sgemm_bias_kernel<<<grid, 256>>>(x, Wqkv, bqkv, qkv, MROWS, 3 * CCH, CCH);
    }

    // 2) Causal flash attention
    {
        const int smem_bytes = (2 * BKV * KSTR + BQ * SSTR) * (int)sizeof(float);
        cudaFuncSetAttribute(attn_kernel, cudaFuncAttributeMaxDynamicSharedMemorySize, smem_bytes);
        dim3 grid(TT / BQ, HH, BB);
        attn_kernel<<<grid, BQ, smem_bytes>>>(qkv, att);
    }

    // 3) Output projection: [4096,1024] @ [1024,1024] + bias
    {
        dim3 grid(CCH / 128, MROWS / 128);
        sgemm_bias_kernel<<<grid, 256>>>(att, Wproj, bproj, out, MROWS, CCH, CCH);
    }
}

// round 4
// speedup vs baseline: 2.9147x; 2.9147x over previous
#include <cuda_runtime.h>
#include <cstdint>

#define BB 2
#define TT 2048
#define CCH 1024
#define HH 16
#define DD 64
#define MROWS (BB * TT)       // 4096
#define NEG_BIG (-1e30f)

__device__ float g_qkv[(size_t)MROWS * 3 * CCH];  // [4096, 3072]
__device__ float g_att[(size_t)MROWS * CCH];      // [4096, 1024]

// ---------------------------------------------------------------------------
// Helpers: tf32 convert + m16n8k8 mma
// ---------------------------------------------------------------------------
__device__ __forceinline__ uint32_t f2tf32(float f) {
    uint32_t r;
    asm("cvt.rna.tf32.f32 %0, %1;" : "=r"(r) : "f"(f));
    return r;
}

__device__ __forceinline__ void mma_tf32(float c[4], const uint32_t a[4],
                                         uint32_t b0, uint32_t b1) {
    asm volatile(
        "mma.sync.aligned.m16n8k8.row.col.f32.tf32.tf32.f32 "
        "{%0,%1,%2,%3}, {%4,%5,%6,%7}, {%8,%9}, {%0,%1,%2,%3};\n"
        : "+f"(c[0]), "+f"(c[1]), "+f"(c[2]), "+f"(c[3])
        : "r"(a[0]), "r"(a[1]), "r"(a[2]), "r"(a[3]), "r"(b0), "r"(b1));
}

// ---------------------------------------------------------------------------
// TF32 GEMM + bias: C[M,N] = A[M,K] @ B[K,N] + bias[N]
// BM=BN=128, BK=16, 256 threads (8 warps, warp tile 64x32).
// ---------------------------------------------------------------------------
#define GST 136   // smem row stride (floats), conflict-free frag loads
__global__ __launch_bounds__(256)
void gemm_tf32_kernel(const float* __restrict__ A, const float* __restrict__ B,
                      const float* __restrict__ bias, float* __restrict__ C,
                      int M, int N, int K) {
    __shared__ float As[16][GST];  // [k][m]
    __shared__ float Bs[16][GST];  // [k][n]

    const int tid = threadIdx.x;
    const int wid = tid >> 5, lane = tid & 31;
    const int g = lane >> 2, tg = lane & 3;
    const int wm = (wid & 1) * 64;   // warp m offset
    const int wn = (wid >> 1) * 32;  // warp n offset
    const int rowBase = blockIdx.y * 128;
    const int colBase = blockIdx.x * 128;

    float c[4][4][4];  // [mt][nt][reg]
#pragma unroll
    for (int mt = 0; mt < 4; mt++)
#pragma unroll
        for (int nt = 0; nt < 4; nt++)
#pragma unroll
            for (int r = 0; r < 4; r++) c[mt][nt][r] = 0.f;

    for (int k0 = 0; k0 < K; k0 += 16) {
        // Load A tile 128x16 (512 float4s), transpose into As[k][m]
#pragma unroll
        for (int i = 0; i < 2; i++) {
            const int idx = tid * 2 + i;
            const int row = idx >> 2, kc = (idx & 3) * 4;
            float4 av = *reinterpret_cast<const float4*>(
                &A[(size_t)(rowBase + row) * K + k0 + kc]);
            As[kc + 0][row] = av.x;
            As[kc + 1][row] = av.y;
            As[kc + 2][row] = av.z;
            As[kc + 3][row] = av.w;
        }
        // Load B tile 16x128
#pragma unroll
        for (int i = 0; i < 2; i++) {
            const int idx = tid * 2 + i;
            const int row = idx >> 5, col = (idx & 31) * 4;
            *reinterpret_cast<float4*>(&Bs[row][col]) =
                *reinterpret_cast<const float4*>(&B[(size_t)(k0 + row) * N + colBase + col]);
        }
        __syncthreads();

#pragma unroll
        for (int ks = 0; ks < 2; ks++) {
            const int k8 = ks * 8;
            uint32_t a[4][4];
#pragma unroll
            for (int mt = 0; mt < 4; mt++) {
                const int mb = wm + mt * 16;
                a[mt][0] = f2tf32(As[k8 + tg][mb + g]);
                a[mt][1] = f2tf32(As[k8 + tg][mb + g + 8]);
                a[mt][2] = f2tf32(As[k8 + tg + 4][mb + g]);
                a[mt][3] = f2tf32(As[k8 + tg + 4][mb + g + 8]);
            }
#pragma unroll
            for (int nt = 0; nt < 4; nt++) {
                const int nb = wn + nt * 8;
                uint32_t b0 = f2tf32(Bs[k8 + tg][nb + g]);
                uint32_t b1 = f2tf32(Bs[k8 + tg + 4][nb + g]);
#pragma unroll
                for (int mt = 0; mt < 4; mt++) mma_tf32(c[mt][nt], a[mt], b0, b1);
            }
        }
        __syncthreads();
    }

    // Epilogue with bias (c0,c1 contiguous cols; c2,c3 at row+8)
#pragma unroll
    for (int mt = 0; mt < 4; mt++) {
        const int r0 = rowBase + wm + mt * 16 + g;
#pragma unroll
        for (int nt = 0; nt < 4; nt++) {
            const int col = colBase + wn + nt * 8 + tg * 2;
            const float bx = bias[col], by = bias[col + 1];
            float2 o0 = {c[mt][nt][0] + bx, c[mt][nt][1] + by};
            float2 o1 = {c[mt][nt][2] + bx, c[mt][nt][3] + by};
            *reinterpret_cast<float2*>(&C[(size_t)r0 * N + col]) = o0;
            *reinterpret_cast<float2*>(&C[(size_t)(r0 + 8) * N + col]) = o1;
        }
    }
}

// ---------------------------------------------------------------------------
// TF32 flash attention (causal). Block = 128 threads (4 warps).
// BQ = BKV = 64. Warp w owns q rows [w*16, w*16+16).
// qkv layout [M, 3C]; out [M, C] (b,t,h,d).
// ---------------------------------------------------------------------------
#define AST 68  // smem row stride (floats)

__global__ __launch_bounds__(128)
void attn_tc_kernel(const float* __restrict__ qkv, float* __restrict__ out) {
    extern __shared__ float smem[];
    float* Qs = smem;                 // [64][AST] -> reused as Ps
    float* Ks = smem + 64 * AST;
    float* Vs = smem + 2 * 64 * AST;
    float* Ps = Qs;

    const int qb = blockIdx.x, h = blockIdx.y, b = blockIdx.z;
    const int tid = threadIdx.x;
    const int w = tid >> 5, lane = tid & 31;
    const int g = lane >> 2, tg = lane & 3;

    // Load Q tile 64x64 (1024 float4s, 8 per thread)
#pragma unroll
    for (int i = 0; i < 8; i++) {
        const int idx = i * 128 + tid;
        const int row = idx >> 4, c4 = (idx & 15) * 4;
        const size_t gofs = ((size_t)(b * TT + qb * 64 + row)) * (3 * CCH) + h * DD + c4;
        *reinterpret_cast<float4*>(&Qs[row * AST + c4]) =
            *reinterpret_cast<const float4*>(&qkv[gofs]);
    }
    __syncthreads();

    // Q fragments in registers, softmax scale folded in
    uint32_t qf[8][4];
#pragma unroll
    for (int ks = 0; ks < 8; ks++) {
        const int d0 = ks * 8;
        qf[ks][0] = f2tf32(0.125f * Qs[(w * 16 + g) * AST + d0 + tg]);
        qf[ks][1] = f2tf32(0.125f * Qs[(w * 16 + g + 8) * AST + d0 + tg]);
        qf[ks][2] = f2tf32(0.125f * Qs[(w * 16 + g) * AST + d0 + tg + 4]);
        qf[ks][3] = f2tf32(0.125f * Qs[(w * 16 + g + 8) * AST + d0 + tg + 4]);
    }

    float O[8][4];
#pragma unroll
    for (int nt = 0; nt < 8; nt++)
#pragma unroll
        for (int r = 0; r < 4; r++) O[nt][r] = 0.f;
    float m0 = NEG_BIG, m1 = NEG_BIG, l0 = 0.f, l1 = 0.f;

    for (int kt = 0; kt <= qb; kt++) {
        // Load K/V tiles
#pragma unroll
        for (int i = 0; i < 8; i++) {
            const int idx = i * 128 + tid;
            const int row = idx >> 4, c4 = (idx & 15) * 4;
            const size_t gofs = ((size_t)(b * TT + kt * 64 + row)) * (3 * CCH) + h * DD + c4;
            *reinterpret_cast<float4*>(&Ks[row * AST + c4]) =
                *reinterpret_cast<const float4*>(&qkv[gofs + CCH]);
            *reinterpret_cast<float4*>(&Vs[row * AST + c4]) =
                *reinterpret_cast<const float4*>(&qkv[gofs + 2 * CCH]);
        }
        __syncthreads();

        const bool diag = (kt == qb);
        const int ntc = diag ? (2 * w + 2) : 8;  // causal n-tile cutoff

        // S = Q K^T (scaled)
        float s[8][4];
#pragma unroll
        for (int nt = 0; nt < 8; nt++)
#pragma unroll
            for (int r = 0; r < 4; r++) s[nt][r] = NEG_BIG;

        for (int nt = 0; nt < ntc; nt++) {
#pragma unroll
            for (int r = 0; r < 4; r++) s[nt][r] = 0.f;
#pragma unroll
            for (int ks = 0; ks < 8; ks++) {
                uint32_t b0 = f2tf32(Ks[(nt * 8 + g) * AST + ks * 8 + tg]);
                uint32_t b1 = f2tf32(Ks[(nt * 8 + g) * AST + ks * 8 + tg + 4]);
                mma_tf32(s[nt], qf[ks], b0, b1);
            }
        }

        // Causal mask on diagonal tile
        if (diag) {
            const int r0 = w * 16 + g, r1 = r0 + 8;
            for (int nt = 0; nt < ntc; nt++) {
                const int cb = nt * 8 + tg * 2;
                if (cb > r0) s[nt][0] = NEG_BIG;
                if (cb + 1 > r0) s[nt][1] = NEG_BIG;
                if (cb > r1) s[nt][2] = NEG_BIG;
                if (cb + 1 > r1) s[nt][3] = NEG_BIG;
            }
        }

        // Online softmax (rows g and g+8; lanes sharing a row = same g, tg 0..3)
        float mt0 = NEG_BIG, mt1 = NEG_BIG;
        for (int nt = 0; nt < ntc; nt++) {
            mt0 = fmaxf(mt0, fmaxf(s[nt][0], s[nt][1]));
            mt1 = fmaxf(mt1, fmaxf(s[nt][2], s[nt][3]));
        }
        mt0 = fmaxf(mt0, __shfl_xor_sync(0xffffffffu, mt0, 1));
        mt0 = fmaxf(mt0, __shfl_xor_sync(0xffffffffu, mt0, 2));
        mt1 = fmaxf(mt1, __shfl_xor_sync(0xffffffffu, mt1, 1));
        mt1 = fmaxf(mt1, __shfl_xor_sync(0xffffffffu, mt1, 2));
        const float nm0 = fmaxf(m0, mt0), nm1 = fmaxf(m1, mt1);
        const float corr0 = __expf(m0 - nm0), corr1 = __expf(m1 - nm1);

        float rs0 = 0.f, rs1 = 0.f;
        for (int nt = 0; nt < ntc; nt++) {
            float p0 = __expf(s[nt][0] - nm0);
            float p1 = __expf(s[nt][1] - nm0);
            float p2 = __expf(s[nt][2] - nm1);
            float p3 = __expf(s[nt][3] - nm1);
            s[nt][0] = p0; s[nt][1] = p1; s[nt][2] = p2; s[nt][3] = p3;
            rs0 += p0 + p1;
            rs1 += p2 + p3;
        }
        rs0 += __shfl_xor_sync(0xffffffffu, rs0, 1);
        rs0 += __shfl_xor_sync(0xffffffffu, rs0, 2);
        rs1 += __shfl_xor_sync(0xffffffffu, rs1, 1);
        rs1 += __shfl_xor_sync(0xffffffffu, rs1, 2);
        l0 = l0 * corr0 + rs0;
        l1 = l1 * corr1 + rs1;
        m0 = nm0; m1 = nm1;
#pragma unroll
        for (int nt = 0; nt < 8; nt++) {
            O[nt][0] *= corr0; O[nt][1] *= corr0;
            O[nt][2] *= corr1; O[nt][3] *= corr1;
        }

        // Stage P (warp-local rows only) to re-fragment
        for (int nt = 0; nt < ntc; nt++) {
            float2 p0 = {s[nt][0], s[nt][1]};
            float2 p1 = {s[nt][2], s[nt][3]};
            *reinterpret_cast<float2*>(&Ps[(w * 16 + g) * AST + nt * 8 + tg * 2]) = p0;
            *reinterpret_cast<float2*>(&Ps[(w * 16 + g + 8) * AST + nt * 8 + tg * 2]) = p1;
        }
        __syncwarp();

        // O += P V
        for (int ks = 0; ks < ntc; ks++) {
            uint32_t a[4];
            a[0] = f2tf32(Ps[(w * 16 + g) * AST + ks * 8 + tg]);
            a[1] = f2tf32(Ps[(w * 16 + g + 8) * AST + ks * 8 + tg]);
            a[2] = f2tf32(Ps[(w * 16 + g) * AST + ks * 8 + tg + 4]);
            a[3] = f2tf32(Ps[(w * 16 + g + 8) * AST + ks * 8 + tg + 4]);
#pragma unroll
            for (int nt = 0; nt < 8; nt++) {
                uint32_t b0 = f2tf32(Vs[(ks * 8 + tg) * AST + nt * 8 + g]);
                uint32_t b1 = f2tf32(Vs[(ks * 8 + tg + 4) * AST + nt * 8 + g]);
                mma_tf32(O[nt], a, b0, b1);
            }
        }
        __syncthreads();
    }

    // Epilogue
    const float inv0 = 1.f / l0, inv1 = 1.f / l1;
    const int row0 = qb * 64 + w * 16 + g;
#pragma unroll
    for (int nt = 0; nt < 8; nt++) {
        const int col = h * DD + nt * 8 + tg * 2;
        float2 o0 = {O[nt][0] * inv0, O[nt][1] * inv0};
        float2 o1 = {O[nt][2] * inv1, O[nt][3] * inv1};
        *reinterpret_cast<float2*>(&out[(size_t)(b * TT + row0) * CCH + col]) = o0;
        *reinterpret_cast<float2*>(&out[(size_t)(b * TT + row0 + 8) * CCH + col]) = o1;
    }
}

// ---------------------------------------------------------------------------
extern "C" void kernel_launch(void* const* d_in, const int* in_sizes, int n_in,
                              void* d_out, int out_size) {
    const float* x     = (const float*)d_in[0];
    const float* Wqkv  = (const float*)d_in[1];
    const float* bqkv  = (const float*)d_in[2];
    const float* Wproj = (const float*)d_in[3];
    const float* bproj = (const float*)d_in[4];
    float* out = (float*)d_out;

    float *qkv, *att;
    cudaGetSymbolAddress((void**)&qkv, g_qkv);
    cudaGetSymbolAddress((void**)&att, g_att);

    // 1) QKV projection
    {
        dim3 grid(3 * CCH / 128, MROWS / 128);
        gemm_tf32_kernel<<<grid, 256>>>(x, Wqkv, bqkv, qkv, MROWS, 3 * CCH, CCH);
    }
    // 2) Flash attention (tf32 tensor cores)
    {
        const int smem_bytes = 3 * 64 * AST * (int)sizeof(float);
        cudaFuncSetAttribute(attn_tc_kernel, cudaFuncAttributeMaxDynamicSharedMemorySize,
                             smem_bytes);
        dim3 grid(TT / 64, HH, BB);
        attn_tc_kernel<<<grid, 128, smem_bytes>>>(qkv, att);
    }
    // 3) Output projection
    {
        dim3 grid(CCH / 128, MROWS / 128);
        gemm_tf32_kernel<<<grid, 256>>>(att, Wproj, bproj, out, MROWS, CCH, CCH);
    }
}

// round 5
// speedup vs baseline: 4.3012x; 1.4757x over previous
#include <cuda_runtime.h>
#include <cstdint>

#define BB 2
#define TT 2048
#define CCH 1024
#define HH 16
#define DD 64
#define MROWS (BB * TT)       // 4096
#define NEG_BIG (-1e30f)

__device__ float g_qkv[(size_t)MROWS * 3 * CCH];  // [4096, 3072]
__device__ float g_att[(size_t)MROWS * CCH];      // [4096, 1024]

// ---------------------------------------------------------------------------
// Helpers
// ---------------------------------------------------------------------------
__device__ __forceinline__ float tf32r(float f) {   // round to tf32, keep as float
    uint32_t r;
    asm("cvt.rna.tf32.f32 %0, %1;" : "=r"(r) : "f"(f));
    return __uint_as_float(r);
}
__device__ __forceinline__ uint32_t fb(float f) { return __float_as_uint(f); }

__device__ __forceinline__ void mma_tf32(float c[4], const uint32_t a[4],
                                         uint32_t b0, uint32_t b1) {
    asm volatile(
        "mma.sync.aligned.m16n8k8.row.col.f32.tf32.tf32.f32 "
        "{%0,%1,%2,%3}, {%4,%5,%6,%7}, {%8,%9}, {%0,%1,%2,%3};\n"
        : "+f"(c[0]), "+f"(c[1]), "+f"(c[2]), "+f"(c[3])
        : "r"(a[0]), "r"(a[1]), "r"(a[2]), "r"(a[3]), "r"(b0), "r"(b1));
}

// ---------------------------------------------------------------------------
// TF32 GEMM + bias: C = A[M,K] @ B[K,N] + bias.  128x128 block, 128 threads,
// 4 warps each 64x64.  BK=16, reg-prefetch double buffer, tf32 stored in smem.
// A smem uses XOR swizzle: column m stored at m ^ (((k>>2)&3)<<3).
// ---------------------------------------------------------------------------
#define GAS 136
#define GBS 136
__global__ __launch_bounds__(128)
void gemm_tf32_kernel(const float* __restrict__ A, const float* __restrict__ B,
                      const float* __restrict__ bias, float* __restrict__ C,
                      int M, int N, int K) {
    __shared__ float As[16][GAS];
    __shared__ float Bs[16][GBS];

    const int tid = threadIdx.x;
    const int w = tid >> 5, lane = tid & 31;
    const int g = lane >> 2, tg = lane & 3;
    const int wm = (w & 1) * 64, wn = (w >> 1) * 64;
    const int rowBase = blockIdx.y * 128;
    const int colBase = blockIdx.x * 128;

    // load-index precompute
    int aRow[4], aKc[4], bRow[4], bCol[4];
#pragma unroll
    for (int i = 0; i < 4; i++) {
        int idx = i * 128 + tid;
        aRow[i] = idx >> 2; aKc[i] = (idx & 3) * 4;
        bRow[i] = idx >> 5; bCol[i] = (idx & 31) * 4;
    }

    float4 pa[4], pb[4];
#pragma unroll
    for (int i = 0; i < 4; i++) {
        pa[i] = *reinterpret_cast<const float4*>(&A[(size_t)(rowBase + aRow[i]) * K + aKc[i]]);
        pb[i] = *reinterpret_cast<const float4*>(&B[(size_t)bRow[i] * N + colBase + bCol[i]]);
    }
    // store stage 0 (cvt + swizzle)
#pragma unroll
    for (int i = 0; i < 4; i++) {
        float v[4] = {pa[i].x, pa[i].y, pa[i].z, pa[i].w};
#pragma unroll
        for (int j = 0; j < 4; j++) {
            int k = aKc[i] + j;
            As[k][aRow[i] ^ (((k >> 2) & 3) << 3)] = tf32r(v[j]);
        }
        float4 bo = {tf32r(pb[i].x), tf32r(pb[i].y), tf32r(pb[i].z), tf32r(pb[i].w)};
        *reinterpret_cast<float4*>(&Bs[bRow[i]][bCol[i]]) = bo;
    }
    __syncthreads();

    float acc[4][8][4];
#pragma unroll
    for (int mt = 0; mt < 4; mt++)
#pragma unroll
        for (int nt = 0; nt < 8; nt++)
#pragma unroll
            for (int r = 0; r < 4; r++) acc[mt][nt][r] = 0.f;

    for (int k0 = 0; k0 < K; k0 += 16) {
        const bool nxt = (k0 + 16 < K);
        if (nxt) {
#pragma unroll
            for (int i = 0; i < 4; i++) {
                pa[i] = *reinterpret_cast<const float4*>(
                    &A[(size_t)(rowBase + aRow[i]) * K + k0 + 16 + aKc[i]]);
                pb[i] = *reinterpret_cast<const float4*>(
                    &B[(size_t)(k0 + 16 + bRow[i]) * N + colBase + bCol[i]]);
            }
        }
        // compute current stage
#pragma unroll
        for (int ks = 0; ks < 2; ks++) {
            const int k8 = ks * 8;
            const int sw0 = ((k8 >> 2) & 3) << 3;
            const int sw1 = (((k8 >> 2) + 1) & 3) << 3;
            uint32_t a[4][4];
#pragma unroll
            for (int mt = 0; mt < 4; mt++) {
                const int mb = wm + mt * 16;
                a[mt][0] = fb(As[k8 + tg][(mb + g) ^ sw0]);
                a[mt][1] = fb(As[k8 + tg][(mb + g + 8) ^ sw0]);
                a[mt][2] = fb(As[k8 + tg + 4][(mb + g) ^ sw1]);
                a[mt][3] = fb(As[k8 + tg + 4][(mb + g + 8) ^ sw1]);
            }
#pragma unroll
            for (int nt = 0; nt < 8; nt++) {
                uint32_t b0 = fb(Bs[k8 + tg][wn + nt * 8 + g]);
                uint32_t b1 = fb(Bs[k8 + tg + 4][wn + nt * 8 + g]);
#pragma unroll
                for (int mt = 0; mt < 4; mt++) mma_tf32(acc[mt][nt], a[mt], b0, b1);
            }
        }
        if (nxt) {
            __syncthreads();
#pragma unroll
            for (int i = 0; i < 4; i++) {
                float v[4] = {pa[i].x, pa[i].y, pa[i].z, pa[i].w};
#pragma unroll
                for (int j = 0; j < 4; j++) {
                    int k = aKc[i] + j;
                    As[k][aRow[i] ^ (((k >> 2) & 3) << 3)] = tf32r(v[j]);
                }
                float4 bo = {tf32r(pb[i].x), tf32r(pb[i].y), tf32r(pb[i].z), tf32r(pb[i].w)};
                *reinterpret_cast<float4*>(&Bs[bRow[i]][bCol[i]]) = bo;
            }
            __syncthreads();
        }
    }

    // epilogue
#pragma unroll
    for (int mt = 0; mt < 4; mt++) {
        const int r0 = rowBase + wm + mt * 16 + g;
#pragma unroll
        for (int nt = 0; nt < 8; nt++) {
            const int col = colBase + wn + nt * 8 + tg * 2;
            const float bx = bias[col], by = bias[col + 1];
            float2 o0 = {acc[mt][nt][0] + bx, acc[mt][nt][1] + by};
            float2 o1 = {acc[mt][nt][2] + bx, acc[mt][nt][3] + by};
            *reinterpret_cast<float2*>(&C[(size_t)r0 * N + col]) = o0;
            *reinterpret_cast<float2*>(&C[(size_t)(r0 + 8) * N + col]) = o1;
        }
    }
}

// ---------------------------------------------------------------------------
// TF32 flash attention (causal).  128 threads (4 warps), BQ=128 (32 q rows
// per warp), BKV=64.  K/V/P stored tf32 in smem; all frag loops fully
// unrolled with predicates so fragment arrays stay in registers.
// ---------------------------------------------------------------------------
#define QST 68
#define KST 68
#define VST 72

__global__ __launch_bounds__(128)
void attn_tc_kernel(const float* __restrict__ qkv, float* __restrict__ out) {
    extern __shared__ float smem[];
    float* Qs = smem;                      // [128][QST]  (reused as Ps)
    float* Ks = smem + 128 * QST;          // [64][KST]
    float* Vs = smem + 128 * QST + 64 * KST;  // [64][VST]
    float* Ps = Qs;

    const int qb = (gridDim.x - 1) - blockIdx.x;   // heavy blocks first
    const int h = blockIdx.y, b = blockIdx.z;
    const int tid = threadIdx.x;
    const int w = tid >> 5, lane = tid & 31;
    const int g = lane >> 2, tg = lane & 3;

    // Load Q tile 128x64 (raw fp32)
#pragma unroll
    for (int i = 0; i < 16; i++) {
        const int idx = i * 128 + tid;
        const int row = idx >> 4, c4 = (idx & 15) * 4;
        const size_t gofs = ((size_t)(b * TT + qb * 128 + row)) * (3 * CCH) + h * DD + c4;
        *reinterpret_cast<float4*>(&Qs[row * QST + c4]) =
            *reinterpret_cast<const float4*>(&qkv[gofs]);
    }
    __syncthreads();

    // Q fragments (scale folded, tf32)
    uint32_t qf[2][8][4];
#pragma unroll
    for (int mt = 0; mt < 2; mt++) {
        const int r0 = w * 32 + mt * 16 + g;
#pragma unroll
        for (int ks = 0; ks < 8; ks++) {
            const int d0 = ks * 8;
            qf[mt][ks][0] = fb(tf32r(0.125f * Qs[r0 * QST + d0 + tg]));
            qf[mt][ks][1] = fb(tf32r(0.125f * Qs[(r0 + 8) * QST + d0 + tg]));
            qf[mt][ks][2] = fb(tf32r(0.125f * Qs[r0 * QST + d0 + tg + 4]));
            qf[mt][ks][3] = fb(tf32r(0.125f * Qs[(r0 + 8) * QST + d0 + tg + 4]));
        }
    }

    float O[2][8][4];
#pragma unroll
    for (int mt = 0; mt < 2; mt++)
#pragma unroll
        for (int nt = 0; nt < 8; nt++)
#pragma unroll
            for (int r = 0; r < 4; r++) O[mt][nt][r] = 0.f;
    float mx[2][2] = {{NEG_BIG, NEG_BIG}, {NEG_BIG, NEG_BIG}};
    float l[2][2] = {{0.f, 0.f}, {0.f, 0.f}};

    const int qmin = qb * 128 + w * 32;
    const int ktmax = 2 * qb + 1;

    for (int kt = 0; kt <= ktmax; kt++) {
        // K/V tile load (tf32-converted)
#pragma unroll
        for (int i = 0; i < 8; i++) {
            const int idx = i * 128 + tid;
            const int row = idx >> 4, c4 = (idx & 15) * 4;
            const size_t gofs = ((size_t)(b * TT + kt * 64 + row)) * (3 * CCH) + h * DD + c4;
            float4 kv = *reinterpret_cast<const float4*>(&qkv[gofs + CCH]);
            float4 vv = *reinterpret_cast<const float4*>(&qkv[gofs + 2 * CCH]);
            float4 ko = {tf32r(kv.x), tf32r(kv.y), tf32r(kv.z), tf32r(kv.w)};
            float4 vo = {tf32r(vv.x), tf32r(vv.y), tf32r(vv.z), tf32r(vv.w)};
            *reinterpret_cast<float4*>(&Ks[row * KST + c4]) = ko;
            *reinterpret_cast<float4*>(&Vs[row * VST + c4]) = vo;
        }
        __syncthreads();

        int rem = ((qmin + 31 - kt * 64) >> 3) + 1;
        const int ntc = rem < 8 ? rem : 8;
        if (ntc > 0) {
            const bool needmask = (kt * 64 + 63 > qmin);

            // S = Q K^T
            float s[2][8][4];
#pragma unroll
            for (int nt = 0; nt < 8; nt++) {
                if (nt < ntc) {
#pragma unroll
                    for (int r = 0; r < 4; r++) { s[0][nt][r] = 0.f; s[1][nt][r] = 0.f; }
#pragma unroll
                    for (int ks = 0; ks < 8; ks++) {
                        uint32_t b0 = fb(Ks[(nt * 8 + g) * KST + ks * 8 + tg]);
                        uint32_t b1 = fb(Ks[(nt * 8 + g) * KST + ks * 8 + tg + 4]);
                        mma_tf32(s[0][nt], qf[0][ks], b0, b1);
                        mma_tf32(s[1][nt], qf[1][ks], b0, b1);
                    }
                }
            }

            if (needmask) {
#pragma unroll
                for (int mt = 0; mt < 2; mt++) {
                    const int r0 = qmin + mt * 16 + g, r1 = r0 + 8;
#pragma unroll
                    for (int nt = 0; nt < 8; nt++) {
                        if (nt < ntc) {
                            const int c0 = kt * 64 + nt * 8 + tg * 2, c1 = c0 + 1;
                            if (c0 > r0) s[mt][nt][0] = NEG_BIG;
                            if (c1 > r0) s[mt][nt][1] = NEG_BIG;
                            if (c0 > r1) s[mt][nt][2] = NEG_BIG;
                            if (c1 > r1) s[mt][nt][3] = NEG_BIG;
                        }
                    }
                }
            }

            // online softmax
#pragma unroll
            for (int mt = 0; mt < 2; mt++) {
                float mt0 = NEG_BIG, mt1 = NEG_BIG;
#pragma unroll
                for (int nt = 0; nt < 8; nt++) {
                    if (nt < ntc) {
                        mt0 = fmaxf(mt0, fmaxf(s[mt][nt][0], s[mt][nt][1]));
                        mt1 = fmaxf(mt1, fmaxf(s[mt][nt][2], s[mt][nt][3]));
                    }
                }
                mt0 = fmaxf(mt0, __shfl_xor_sync(0xffffffffu, mt0, 1));
                mt0 = fmaxf(mt0, __shfl_xor_sync(0xffffffffu, mt0, 2));
                mt1 = fmaxf(mt1, __shfl_xor_sync(0xffffffffu, mt1, 1));
                mt1 = fmaxf(mt1, __shfl_xor_sync(0xffffffffu, mt1, 2));
                const float nm0 = fmaxf(mx[mt][0], mt0), nm1 = fmaxf(mx[mt][1], mt1);
                const float c0 = __expf(mx[mt][0] - nm0), c1 = __expf(mx[mt][1] - nm1);
                float rs0 = 0.f, rs1 = 0.f;
#pragma unroll
                for (int nt = 0; nt < 8; nt++) {
                    if (nt < ntc) {
                        float p0 = __expf(s[mt][nt][0] - nm0);
                        float p1 = __expf(s[mt][nt][1] - nm0);
                        float p2 = __expf(s[mt][nt][2] - nm1);
                        float p3 = __expf(s[mt][nt][3] - nm1);
                        s[mt][nt][0] = p0; s[mt][nt][1] = p1;
                        s[mt][nt][2] = p2; s[mt][nt][3] = p3;
                        rs0 += p0 + p1; rs1 += p2 + p3;
                    }
                }
                rs0 += __shfl_xor_sync(0xffffffffu, rs0, 1);
                rs0 += __shfl_xor_sync(0xffffffffu, rs0, 2);
                rs1 += __shfl_xor_sync(0xffffffffu, rs1, 1);
                rs1 += __shfl_xor_sync(0xffffffffu, rs1, 2);
                l[mt][0] = l[mt][0] * c0 + rs0;
                l[mt][1] = l[mt][1] * c1 + rs1;
                mx[mt][0] = nm0; mx[mt][1] = nm1;
#pragma unroll
                for (int nt = 0; nt < 8; nt++) {
                    O[mt][nt][0] *= c0; O[mt][nt][1] *= c0;
                    O[mt][nt][2] *= c1; O[mt][nt][3] *= c1;
                }
            }

            // stage P (tf32)
#pragma unroll
            for (int mt = 0; mt < 2; mt++) {
                const int r0 = w * 32 + mt * 16 + g;
#pragma unroll
                for (int nt = 0; nt < 8; nt++) {
                    if (nt < ntc) {
                        float2 p0 = {tf32r(s[mt][nt][0]), tf32r(s[mt][nt][1])};
                        float2 p1 = {tf32r(s[mt][nt][2]), tf32r(s[mt][nt][3])};
                        *reinterpret_cast<float2*>(&Ps[r0 * QST + nt * 8 + tg * 2]) = p0;
                        *reinterpret_cast<float2*>(&Ps[(r0 + 8) * QST + nt * 8 + tg * 2]) = p1;
                    }
                }
            }
            __syncwarp();

            // O += P V
#pragma unroll
            for (int ks = 0; ks < 8; ks++) {
                if (ks < ntc) {
                    uint32_t a0[4], a1[4];
                    const int rA = w * 32 + g;
                    a0[0] = fb(Ps[rA * QST + ks * 8 + tg]);
                    a0[1] = fb(Ps[(rA + 8) * QST + ks * 8 + tg]);
                    a0[2] = fb(Ps[rA * QST + ks * 8 + tg + 4]);
                    a0[3] = fb(Ps[(rA + 8) * QST + ks * 8 + tg + 4]);
                    a1[0] = fb(Ps[(rA + 16) * QST + ks * 8 + tg]);
                    a1[1] = fb(Ps[(rA + 24) * QST + ks * 8 + tg]);
                    a1[2] = fb(Ps[(rA + 16) * QST + ks * 8 + tg + 4]);
                    a1[3] = fb(Ps[(rA + 24) * QST + ks * 8 + tg + 4]);
#pragma unroll
                    for (int nt = 0; nt < 8; nt++) {
                        uint32_t b0 = fb(Vs[(ks * 8 + tg) * VST + nt * 8 + g]);
                        uint32_t b1 = fb(Vs[(ks * 8 + tg + 4) * VST + nt * 8 + g]);
                        mma_tf32(O[0][nt], a0, b0, b1);
                        mma_tf32(O[1][nt], a1, b0, b1);
                    }
                }
            }
        }
        __syncthreads();
    }

    // epilogue
#pragma unroll
    for (int mt = 0; mt < 2; mt++) {
        const float inv0 = 1.f / l[mt][0], inv1 = 1.f / l[mt][1];
        const int row0 = qb * 128 + w * 32 + mt * 16 + g;
#pragma unroll
        for (int nt = 0; nt < 8; nt++) {
            const int col = h * DD + nt * 8 + tg * 2;
            float2 o0 = {O[mt][nt][0] * inv0, O[mt][nt][1] * inv0};
            float2 o1 = {O[mt][nt][2] * inv1, O[mt][nt][3] * inv1};
            *reinterpret_cast<float2*>(&out[(size_t)(b * TT + row0) * CCH + col]) = o0;
            *reinterpret_cast<float2*>(&out[(size_t)(b * TT + row0 + 8) * CCH + col]) = o1;
        }
    }
}

// ---------------------------------------------------------------------------
extern "C" void kernel_launch(void* const* d_in, const int* in_sizes, int n_in,
                              void* d_out, int out_size) {
    const float* x     = (const float*)d_in[0];
    const float* Wqkv  = (const float*)d_in[1];
    const float* bqkv  = (const float*)d_in[2];
    const float* Wproj = (const float*)d_in[3];
    const float* bproj = (const float*)d_in[4];
    float* out = (float*)d_out;

    float *qkv, *att;
    cudaGetSymbolAddress((void**)&qkv, g_qkv);
    cudaGetSymbolAddress((void**)&att, g_att);

    // 1) QKV projection
    {
        dim3 grid(3 * CCH / 128, MROWS / 128);
        gemm_tf32_kernel<<<grid, 128>>>(x, Wqkv, bqkv, qkv, MROWS, 3 * CCH, CCH);
    }
    // 2) Flash attention
    {
        const int smem_bytes = (128 * QST + 64 * KST + 64 * VST) * (int)sizeof(float);
        cudaFuncSetAttribute(attn_tc_kernel, cudaFuncAttributeMaxDynamicSharedMemorySize,
                             smem_bytes);
        dim3 grid(TT / 128, HH, BB);
        attn_tc_kernel<<<grid, 128, smem_bytes>>>(qkv, att);
    }
    // 3) Output projection
    {
        dim3 grid(CCH / 128, MROWS / 128);
        gemm_tf32_kernel<<<grid, 128>>>(att, Wproj, bproj, out, MROWS, CCH, CCH);
    }
}